// round 4
// baseline (speedup 1.0000x reference)
#include <cuda_runtime.h>

#define NPIX 4096
#define CC   256
#define CQ   64
#define BB   8
#define ROWS_ALL (2*CQ + CC)   // 384: [q(64) | k(64) | gamma-folded value(256)]

typedef unsigned long long u64;

// ---- packed f32x2 helpers (SASS FFMA2 path; ptxas never emits from C++) ----
__device__ __forceinline__ u64 pack2(float x, float y) {
    u64 r; asm("mov.b64 %0, {%1, %2};" : "=l"(r) : "f"(x), "f"(y)); return r;
}
__device__ __forceinline__ u64 dup2(float x) { return pack2(x, x); }
__device__ __forceinline__ void fma2(u64 &d, u64 a, u64 b) {
    asm("fma.rn.f32x2 %0, %1, %2, %0;" : "+l"(d) : "l"(a), "l"(b));
}
__device__ __forceinline__ float2 unpk(u64 v) {
    float2 f; asm("mov.b64 {%0, %1}, %2;" : "=f"(f.x), "=f"(f.y) : "l"(v)); return f;
}

// ---- scratch (device globals; no runtime allocation allowed) ----
__device__ float g_Q  [BB*CQ*NPIX];          // [b][cq][n]
__device__ float g_K  [BB*CQ*NPIX];          // [b][cq][m]
__device__ float g_VG [(size_t)BB*CC*NPIX];  // [b][c][n], gamma pre-folded
__device__ float g_Wall[ROWS_ALL*CC];
__device__ float g_ball[ROWS_ALL];

// ============================================================
// Kernel 0: build combined weight matrix (gamma folded into V).
// ============================================================
__global__ void build_weights(const float* __restrict__ qw, const float* __restrict__ qb,
                              const float* __restrict__ kw, const float* __restrict__ kb,
                              const float* __restrict__ vw, const float* __restrict__ vb,
                              const float* __restrict__ gw) {
    int r = blockIdx.x;      // 0..383
    int d = threadIdx.x;     // 0..255
    if (r < CQ) {
        g_Wall[r*CC + d] = qw[r*CC + d];
        if (d == 0) g_ball[r] = qb[r];
    } else if (r < 2*CQ) {
        int rr = r - CQ;
        g_Wall[r*CC + d] = kw[rr*CC + d];
        if (d == 0) g_ball[r] = kb[rr];
    } else {
        int c = r - 2*CQ;
        float acc = 0.f;
        for (int cp = 0; cp < CC; ++cp)
            acc = fmaf(gw[c*CC + cp], vw[cp*CC + d], acc);
        g_Wall[r*CC + d] = acc;
        if (d == 0) {
            float bacc = 0.f;
            for (int cp = 0; cp < CC; ++cp)
                bacc = fmaf(gw[c*CC + cp], vb[cp], bacc);
            g_ball[r] = bacc;
        }
    }
}

// ============================================================
// Kernel 1: projection GEMM (packed f32x2). out[384,4096]/batch = Wall @ x[b]
// block 256 threads, tile 64co x 64n, thread 4co x (2x2 packed n).
// ============================================================
__global__ void __launch_bounds__(256) proj_kernel(const float* __restrict__ x) {
    __shared__ float Ws[16][64];   // [k][co]
    __shared__ float Xs[16][64];   // [k][n]
    int b   = blockIdx.z;
    int co0 = blockIdx.y * 64;
    int n0  = blockIdx.x * 64;
    int t   = threadIdx.x;
    int tn  = t % 16;
    int tco = t / 16;
    const float* xb = x + (size_t)b * CC * NPIX;

    u64 acc2[4][2];
    #pragma unroll
    for (int i = 0; i < 4; i++)
        #pragma unroll
        for (int j = 0; j < 2; j++) acc2[i][j] = 0ull;

    for (int k0 = 0; k0 < CC; k0 += 16) {
        {   // Ws[k][co] = Wall[(co0+co)][k0+k]
            int k  = t % 16;
            int co = t / 16;
            #pragma unroll
            for (int i = 0; i < 4; i++)
                Ws[k][co + 16*i] = g_Wall[(co0 + co + 16*i)*CC + k0 + k];
        }
        {   // Xs[k][n] (float4 along n)
            int idx = t * 4;
            int k = idx / 64, n = idx % 64;
            float4 v = *(const float4*)&xb[(size_t)(k0 + k)*NPIX + n0 + n];
            *(float4*)&Xs[k][n] = v;
        }
        __syncthreads();
        #pragma unroll
        for (int k = 0; k < 16; k++) {
            u64 ad[4], bx2[2];
            #pragma unroll
            for (int i = 0; i < 4; i++) ad[i] = dup2(Ws[k][tco + 16*i]);
            #pragma unroll
            for (int j = 0; j < 2; j++) bx2[j] = *(const u64*)&Xs[k][2*tn + 32*j];
            #pragma unroll
            for (int i = 0; i < 4; i++)
                #pragma unroll
                for (int j = 0; j < 2; j++)
                    fma2(acc2[i][j], ad[i], bx2[j]);
        }
        __syncthreads();
    }

    #pragma unroll
    for (int i = 0; i < 4; i++) {
        int co = co0 + tco + 16*i;
        float bias = g_ball[co];
        float* dst;
        if (co < CQ)          dst = g_Q  + ((size_t)b*CQ + co)        * NPIX;
        else if (co < 2*CQ)   dst = g_K  + ((size_t)b*CQ + (co-CQ))   * NPIX;
        else                  dst = g_VG + ((size_t)b*CC + (co-2*CQ)) * NPIX;
        #pragma unroll
        for (int j = 0; j < 2; j++) {
            float2 v = unpk(acc2[i][j]);
            v.x += bias; v.y += bias;
            *(float2*)&dst[n0 + 2*tn + 32*j] = v;
        }
    }
}

// ============================================================
// Kernel 2: fused attention (packed f32x2).
//   out[b,c,m] = bg[c] + sum_n VG[b,c,n] * elu(Q[:,n] . K[:,m]) / N
// grid (64 m-tiles, B=8), 256 threads; output tile [256c x 64m].
// ============================================================
__global__ void __launch_bounds__(256) attn_kernel(float* __restrict__ out,
                                                   const float* __restrict__ gbias) {
    __shared__ float Ks[64][64];   // [cq][m]   (persistent)
    __shared__ float Ss[64][64];   // [m][n]
    __shared__ float U[4096];      // phase1: Qs[cq*64+n]; phase2: VGs[nn*256+c]

    int b  = blockIdx.y;
    int m0 = blockIdx.x * 64;
    int t  = threadIdx.x;

    {   // load K tile once
        int idx = t * 4;
        #pragma unroll
        for (int r = 0; r < 4; r++) {
            int id = idx + r * 1024;
            int cq = id / 64, m = id % 64;
            *(float4*)&Ks[cq][m] =
                *(const float4*)&g_K[((size_t)b*CQ + cq)*NPIX + m0 + m];
        }
    }

    u64 acc2[4][8];   // c-pair (2tc+64*i2, +1) x m (tm8+8*j)
    #pragma unroll
    for (int i = 0; i < 4; i++)
        #pragma unroll
        for (int j = 0; j < 8; j++) acc2[i][j] = 0ull;

    const int t16x = t % 16, t16y = t / 16;  // phase1: n-dir (packed), m-dir
    const int tc   = t % 32, tm8  = t / 32;  // phase2: c-dir (packed), m-dir

    for (int it = 0; it < 64; ++it) {
        int n0 = it * 64;
        __syncthreads();                       // U free
        {   // load Q tile into U: Qs[cq][n]
            int idx = t * 4;
            #pragma unroll
            for (int r = 0; r < 4; r++) {
                int id = idx + r * 1024;
                int cq = id / 64, n = id % 64;
                *(float4*)&U[cq*64 + n] =
                    *(const float4*)&g_Q[((size_t)b*CQ + cq)*NPIX + n0 + n];
            }
        }
        __syncthreads();

        // ---- phase 1: S = Q^T K, elu, /N.  n = 2*t16x + 32*i2 + lane, m = t16y + 16*j
        u64 s2[2][4];
        #pragma unroll
        for (int i = 0; i < 2; i++)
            #pragma unroll
            for (int j = 0; j < 4; j++) s2[i][j] = 0ull;

        #pragma unroll 8
        for (int cq = 0; cq < 64; cq++) {
            u64 qv2[2], kvd[4];
            #pragma unroll
            for (int i = 0; i < 2; i++) qv2[i] = *(const u64*)&U[cq*64 + 2*t16x + 32*i];
            #pragma unroll
            for (int j = 0; j < 4; j++) kvd[j] = dup2(Ks[cq][t16y + 16*j]);
            #pragma unroll
            for (int i = 0; i < 2; i++)
                #pragma unroll
                for (int j = 0; j < 4; j++)
                    fma2(s2[i][j], qv2[i], kvd[j]);
        }
        #pragma unroll
        for (int i = 0; i < 2; i++)
            #pragma unroll
            for (int j = 0; j < 4; j++) {
                float2 v = unpk(s2[i][j]);
                v.x = ((v.x > 0.f) ? v.x : (__expf(v.x) - 1.f)) * (1.0f/4096.0f);
                v.y = ((v.y > 0.f) ? v.y : (__expf(v.y) - 1.f)) * (1.0f/4096.0f);
                *(float2*)&Ss[t16y + 16*j][2*t16x + 32*i] = v;
            }

        // ---- phase 2: O += VG @ S, VG staged 16 n at a time through U ----
        #pragma unroll 1
        for (int ch = 0; ch < 4; ++ch) {
            __syncthreads();
            {   // VGs[nn][c]: each thread owns one c row
                int c = t;
                const float* src = &g_VG[((size_t)b*CC + c)*NPIX + n0 + ch*16];
                #pragma unroll
                for (int r = 0; r < 4; r++) {
                    float4 v = *(const float4*)&src[r*4];
                    U[(r*4+0)*256 + c] = v.x;
                    U[(r*4+1)*256 + c] = v.y;
                    U[(r*4+2)*256 + c] = v.z;
                    U[(r*4+3)*256 + c] = v.w;
                }
            }
            __syncthreads();
            #pragma unroll
            for (int nn = 0; nn < 16; ++nn) {
                u64 vv2[4], svd[8];
                #pragma unroll
                for (int i = 0; i < 4; i++)
                    vv2[i] = *(const u64*)&U[nn*256 + 2*tc + 64*i];       // contiguous c pair
                #pragma unroll
                for (int j = 0; j < 8; j++)
                    svd[j] = dup2(Ss[tm8 + 8*j][ch*16 + nn]);             // broadcast
                #pragma unroll
                for (int i = 0; i < 4; i++)
                    #pragma unroll
                    for (int j = 0; j < 8; j++)
                        fma2(acc2[i][j], vv2[i], svd[j]);
            }
        }
    }

    // ---- epilogue: stage through Ss, add gamma bias, float4 stores ----
    for (int p = 0; p < 4; p++) {   // c block [64p, 64p+64); thread's pair = i2 == p
        __syncthreads();
        #pragma unroll
        for (int j = 0; j < 8; j++) {
            float2 v = unpk(acc2[p][j]);
            Ss[2*tc  ][tm8 + 8*j] = v.x;
            Ss[2*tc+1][tm8 + 8*j] = v.y;
        }
        __syncthreads();
        {
            int idx = t * 4;
            #pragma unroll
            for (int r = 0; r < 4; r++) {
                int id = idx + r * 1024;
                int cc = id / 64, m = id % 64;
                int cg = 64*p + cc;
                float bias = gbias[cg];
                float4 v = *(float4*)&Ss[cc][m];
                v.x += bias; v.y += bias; v.z += bias; v.w += bias;
                *(float4*)&out[((size_t)b*CC + cg)*NPIX + m0 + m] = v;
            }
        }
    }
}

// ============================================================
extern "C" void kernel_launch(void* const* d_in, const int* in_sizes, int n_in,
                              void* d_out, int out_size) {
    const float* x  = (const float*)d_in[0];
    const float* qw = (const float*)d_in[1];
    const float* qb = (const float*)d_in[2];
    const float* kw = (const float*)d_in[3];
    const float* kb = (const float*)d_in[4];
    const float* vw = (const float*)d_in[5];
    const float* vb = (const float*)d_in[6];
    const float* gw = (const float*)d_in[7];
    const float* gb = (const float*)d_in[8];
    float* out = (float*)d_out;

    build_weights<<<ROWS_ALL, 256>>>(qw, qb, kw, kb, vw, vb, gw);
    proj_kernel<<<dim3(64, 6, BB), 256>>>(x);
    attn_kernel<<<dim3(64, BB), 256>>>(out, gb);
}

// round 6
// speedup vs baseline: 3.8750x; 3.8750x over previous
#include <cuda_runtime.h>
#include <cuda_bf16.h>
#include <cstdint>

#define NPIX 4096
#define CC   256
#define CQ   64
#define BB   8
#define ROWS_ALL 384
#define LD   72   // smem row stride in halves (16B-pad => conflict-free frags)

// ================= scratch (device globals) =================
__device__ __nv_bfloat16 g_Qh[(size_t)BB*NPIX*CQ];   // [b][n][cq]
__device__ __nv_bfloat16 g_Ql[(size_t)BB*NPIX*CQ];
__device__ __nv_bfloat16 g_Kh[(size_t)BB*NPIX*CQ];   // [b][m][cq]
__device__ __nv_bfloat16 g_Kl[(size_t)BB*NPIX*CQ];
__device__ __nv_bfloat16 g_VGh[(size_t)BB*CC*NPIX];  // [b][c][n]
__device__ __nv_bfloat16 g_VGl[(size_t)BB*CC*NPIX];
__device__ float g_Wall[ROWS_ALL*CC];
__device__ float g_ball[ROWS_ALL];

// ================= mma.sync helpers (sm_80+ PTX, no arch-feature gate) =====
__device__ __forceinline__ void mma16816(float c[4], const uint32_t a[4], const uint32_t b[2]) {
    asm volatile(
        "mma.sync.aligned.m16n8k16.row.col.f32.bf16.bf16.f32 "
        "{%0,%1,%2,%3}, {%4,%5,%6,%7}, {%8,%9}, {%0,%1,%2,%3};"
        : "+f"(c[0]), "+f"(c[1]), "+f"(c[2]), "+f"(c[3])
        : "r"(a[0]), "r"(a[1]), "r"(a[2]), "r"(a[3]), "r"(b[0]), "r"(b[1]));
}
// A fragment (row-major M16xK16), p -> &tile[(R+g)*LD + C + t4*2]
__device__ __forceinline__ void ldA(uint32_t a[4], const __nv_bfloat16* p) {
    a[0] = *(const uint32_t*)(p);
    a[1] = *(const uint32_t*)(p + 8*LD);
    a[2] = *(const uint32_t*)(p + 8);
    a[3] = *(const uint32_t*)(p + 8*LD + 8);
}
// B fragment (col-major K16xN8), p -> &tile[(N0+g)*LD + C + t4*2]
__device__ __forceinline__ void ldB(uint32_t b[2], const __nv_bfloat16* p) {
    b[0] = *(const uint32_t*)(p);
    b[1] = *(const uint32_t*)(p + 8);
}
// pack two f32 -> bf16x2 (e0 in low half, e1 in high half)
__device__ __forceinline__ uint32_t packbf(float e0, float e1) {
    uint32_t r; asm("cvt.rn.bf16x2.f32 %0, %1, %2;" : "=r"(r) : "f"(e1), "f"(e0)); return r;
}

// elu WITHOUT the /N (deferred): v>0 ? v : exp(v)-1, exp via FFMA poly (no MUFU)
__device__ __forceinline__ float elu_raw(float v) {
    float kf = rintf(v * 1.44269504f);
    float r  = fmaf(kf, -0.693145752f, v);
    r        = fmaf(kf, -1.42860677e-6f, r);
    float p  = 1.38888894e-3f;               // 1/720
    p = fmaf(p, r, 8.33333377e-3f);          // 1/120
    p = fmaf(p, r, 4.16666679e-2f);          // 1/24
    p = fmaf(p, r, 0.166666672f);            // 1/6
    p = fmaf(p, r, 0.5f);
    p = fmaf(p, r, 1.0f);
    p = fmaf(p, r, 1.0f);
    float sc = __uint_as_float((uint32_t)((127 + (int)kf) << 23));
    float e  = fmaf(p, sc, -1.0f);
    return v > 0.f ? v : e;
}

// ================= Kernel 0: weights (gamma folded into V) =================
__global__ void build_weights(const float* __restrict__ qw, const float* __restrict__ qb,
                              const float* __restrict__ kw, const float* __restrict__ kb,
                              const float* __restrict__ vw, const float* __restrict__ vb,
                              const float* __restrict__ gw) {
    int r = blockIdx.x, d = threadIdx.x;
    if (r < CQ) {
        g_Wall[r*CC + d] = qw[r*CC + d];
        if (d == 0) g_ball[r] = qb[r];
    } else if (r < 2*CQ) {
        g_Wall[r*CC + d] = kw[(r-CQ)*CC + d];
        if (d == 0) g_ball[r] = kb[r-CQ];
    } else {
        int c = r - 2*CQ;
        float acc = 0.f;
        for (int cp = 0; cp < CC; ++cp) acc = fmaf(gw[c*CC + cp], vw[cp*CC + d], acc);
        g_Wall[r*CC + d] = acc;
        if (d == 0) {
            float bacc = 0.f;
            for (int cp = 0; cp < CC; ++cp) bacc = fmaf(gw[c*CC + cp], vb[cp], bacc);
            g_ball[r] = bacc;
        }
    }
}

// ================= Kernel 1: projection (fp32), writes split bf16 ==========
__global__ void __launch_bounds__(256) proj_kernel(const float* __restrict__ x) {
    __shared__ float Ws[16][64];
    __shared__ float Xs[16][64];
    int b = blockIdx.z, co0 = blockIdx.y * 64, n0 = blockIdx.x * 64;
    int t = threadIdx.x, tn = t % 16, tco = t / 16;
    const float* xb = x + (size_t)b * CC * NPIX;

    float acc[4][4];
    #pragma unroll
    for (int i = 0; i < 4; i++)
        #pragma unroll
        for (int j = 0; j < 4; j++) acc[i][j] = 0.f;

    for (int k0 = 0; k0 < CC; k0 += 16) {
        {
            int k = t % 16, co = t / 16;
            #pragma unroll
            for (int i = 0; i < 4; i++)
                Ws[k][co + 16*i] = g_Wall[(co0 + co + 16*i)*CC + k0 + k];
        }
        {
            int idx = t * 4, k = idx / 64, n = idx % 64;
            *(float4*)&Xs[k][n] = *(const float4*)&xb[(size_t)(k0 + k)*NPIX + n0 + n];
        }
        __syncthreads();
        #pragma unroll
        for (int k = 0; k < 16; k++) {
            float a[4], bx[4];
            #pragma unroll
            for (int i = 0; i < 4; i++) a[i] = Ws[k][tco + 16*i];
            #pragma unroll
            for (int j = 0; j < 4; j++) bx[j] = Xs[k][tn + 16*j];
            #pragma unroll
            for (int i = 0; i < 4; i++)
                #pragma unroll
                for (int j = 0; j < 4; j++) acc[i][j] = fmaf(a[i], bx[j], acc[i][j]);
        }
        __syncthreads();
    }

    #pragma unroll
    for (int i = 0; i < 4; i++) {
        int co = co0 + tco + 16*i;
        float bias = g_ball[co];
        #pragma unroll
        for (int j = 0; j < 4; j++) {
            int n = n0 + tn + 16*j;
            float s = acc[i][j] + bias;
            __nv_bfloat16 h = __float2bfloat16(s);
            __nv_bfloat16 l = __float2bfloat16(s - __bfloat162float(h));
            if (co < CQ) {
                size_t o = ((size_t)b*NPIX + n)*CQ + co;
                g_Qh[o] = h; g_Ql[o] = l;
            } else if (co < 2*CQ) {
                size_t o = ((size_t)b*NPIX + n)*CQ + (co - CQ);
                g_Kh[o] = h; g_Kl[o] = l;
            } else {
                size_t o = ((size_t)b*CC + (co - 2*CQ))*NPIX + n;
                g_VGh[o] = h; g_VGl[o] = l;
            }
        }
    }
}

// ================= Kernel 2: fused attention via mma.sync ==================
// block 256 threads (8 warps). Out tile: [256c x 64m]. 64 n-iters of 64.
// GEMM1: D1[m][n] = K[m,:].Q[n,:]  (M=m, N=n, K=cq)  -> elu -> split bf16 -> smem
// GEMM2: O[c][m] += VG[c,:n].S[:n,m]  (M=c, N=m, K=n), S^T rows = D1 rows.
#define SM_KH 0
#define SM_KL (64*LD)
#define SM_QH (2*64*LD)
#define SM_QL (3*64*LD)
#define SM_VH (4*64*LD)
#define SM_VL (4*64*LD + 256*LD)
#define SM_SH (4*64*LD + 2*256*LD)
#define SM_SL (5*64*LD + 2*256*LD)
#define SMEM_HALVES (6*64*LD + 2*256*LD)
#define SMEM_BYTES  (SMEM_HALVES*2)

__global__ void __launch_bounds__(256) attn_mma(float* __restrict__ out,
                                                const float* __restrict__ gbias) {
    extern __shared__ __nv_bfloat16 sm[];
    const int tid = threadIdx.x, wid = tid >> 5, lane = tid & 31;
    const int g = lane >> 2, t4 = lane & 3;
    const int b = blockIdx.y, m0 = blockIdx.x * 64;

    const int w1m = (wid & 1) * 32, w1n = (wid >> 1) * 16;   // GEMM1 warp tile [32m x 16n]
    const int w2c = (wid >> 1) * 64, w2m = (wid & 1) * 32;   // GEMM2 warp tile [64c x 32m]

    float acc[4][4][4];
    #pragma unroll
    for (int i = 0; i < 4; i++)
        #pragma unroll
        for (int j = 0; j < 4; j++)
            #pragma unroll
            for (int q = 0; q < 4; q++) acc[i][j][q] = 0.f;

    // ---- K tiles persist for the whole block ----
    {
        const int row = tid >> 3, col = (tid & 7) * 8;
        #pragma unroll
        for (int r = 0; r < 2; r++) {
            int rr = row + 32*r;
            *(uint4*)&sm[SM_KH + rr*LD + col] =
                *(const uint4*)&g_Kh[((size_t)b*NPIX + m0 + rr)*CQ + col];
            *(uint4*)&sm[SM_KL + rr*LD + col] =
                *(const uint4*)&g_Kl[((size_t)b*NPIX + m0 + rr)*CQ + col];
        }
    }

    for (int it = 0; it < 64; ++it) {
        const int n0 = it * 64;
        __syncthreads();   // prev iter's S consumed; Q/VG buffers free
        {   // Q tiles [64n][64cq]
            const int row = tid >> 3, col = (tid & 7) * 8;
            #pragma unroll
            for (int r = 0; r < 2; r++) {
                int rr = row + 32*r;
                *(uint4*)&sm[SM_QH + rr*LD + col] =
                    *(const uint4*)&g_Qh[((size_t)b*NPIX + n0 + rr)*CQ + col];
                *(uint4*)&sm[SM_QL + rr*LD + col] =
                    *(const uint4*)&g_Ql[((size_t)b*NPIX + n0 + rr)*CQ + col];
            }
            // VG tiles [256c][64n]
            #pragma unroll
            for (int r = 0; r < 8; r++) {
                int c = (tid >> 3) + 32*r;
                *(uint4*)&sm[SM_VH + c*LD + col] =
                    *(const uint4*)&g_VGh[((size_t)b*CC + c)*NPIX + n0 + col];
                *(uint4*)&sm[SM_VL + c*LD + col] =
                    *(const uint4*)&g_VGl[((size_t)b*CC + c)*NPIX + n0 + col];
            }
        }
        __syncthreads();

        // ---- GEMM1: D1[m][n], 3-product bf16 split ----
        float sacc[2][2][4];
        #pragma unroll
        for (int i = 0; i < 2; i++)
            #pragma unroll
            for (int j = 0; j < 2; j++)
                #pragma unroll
                for (int q = 0; q < 4; q++) sacc[i][j][q] = 0.f;

        #pragma unroll
        for (int kk = 0; kk < 4; kk++) {
            const int C = kk * 16;
            uint32_t ah[2][4], al[2][4], bh[2][2], bl[2][2];
            #pragma unroll
            for (int i = 0; i < 2; i++) {
                int off = (w1m + 16*i + g)*LD + C + t4*2;
                ldA(ah[i], &sm[SM_KH + off]);
                ldA(al[i], &sm[SM_KL + off]);
            }
            #pragma unroll
            for (int j = 0; j < 2; j++) {
                int off = (w1n + 8*j + g)*LD + C + t4*2;
                ldB(bh[j], &sm[SM_QH + off]);
                ldB(bl[j], &sm[SM_QL + off]);
            }
            #pragma unroll
            for (int i = 0; i < 2; i++)
                #pragma unroll
                for (int j = 0; j < 2; j++) {
                    mma16816(sacc[i][j], ah[i], bh[j]);
                    mma16816(sacc[i][j], al[i], bh[j]);
                    mma16816(sacc[i][j], ah[i], bl[j]);
                }
        }

        // ---- elu + split + store S (hi/lo) ----
        #pragma unroll
        for (int i = 0; i < 2; i++)
            #pragma unroll
            for (int j = 0; j < 2; j++) {
                int row = w1m + 16*i + g;
                int col = w1n + 8*j + t4*2;
                {
                    float e0 = elu_raw(sacc[i][j][0]);
                    float e1 = elu_raw(sacc[i][j][1]);
                    uint32_t ph = packbf(e0, e1);
                    float l0 = e0 - __uint_as_float(ph << 16);
                    float l1 = e1 - __uint_as_float(ph & 0xFFFF0000u);
                    *(uint32_t*)&sm[SM_SH + row*LD + col] = ph;
                    *(uint32_t*)&sm[SM_SL + row*LD + col] = packbf(l0, l1);
                }
                {
                    float e0 = elu_raw(sacc[i][j][2]);
                    float e1 = elu_raw(sacc[i][j][3]);
                    uint32_t ph = packbf(e0, e1);
                    float l0 = e0 - __uint_as_float(ph << 16);
                    float l1 = e1 - __uint_as_float(ph & 0xFFFF0000u);
                    *(uint32_t*)&sm[SM_SH + (row+8)*LD + col] = ph;
                    *(uint32_t*)&sm[SM_SL + (row+8)*LD + col] = packbf(l0, l1);
                }
            }
        __syncthreads();

        // ---- GEMM2: O[c][m] += VG . S ----
        #pragma unroll
        for (int kk = 0; kk < 4; kk++) {
            const int C = kk * 16;
            uint32_t ah[4][4], al[4][4], bh[4][2], bl[4][2];
            #pragma unroll
            for (int i = 0; i < 4; i++) {
                int off = (w2c + 16*i + g)*LD + C + t4*2;
                ldA(ah[i], &sm[SM_VH + off]);
                ldA(al[i], &sm[SM_VL + off]);
            }
            #pragma unroll
            for (int j = 0; j < 4; j++) {
                int off = (w2m + 8*j + g)*LD + C + t4*2;
                ldB(bh[j], &sm[SM_SH + off]);
                ldB(bl[j], &sm[SM_SL + off]);
            }
            #pragma unroll
            for (int i = 0; i < 4; i++)
                #pragma unroll
                for (int j = 0; j < 4; j++) {
                    mma16816(acc[i][j], ah[i], bh[j]);
                    mma16816(acc[i][j], al[i], bh[j]);
                    mma16816(acc[i][j], ah[i], bl[j]);
                }
        }
    }

    // ---- epilogue: out = acc/4096 + gbias[c] ----
    const float inv = 1.0f / 4096.0f;
    #pragma unroll
    for (int i = 0; i < 4; i++) {
        int c  = w2c + 16*i + g;
        float b0 = gbias[c], b8 = gbias[c + 8];
        #pragma unroll
        for (int j = 0; j < 4; j++) {
            int m = m0 + w2m + 8*j + t4*2;
            float2 v0 = { fmaf(acc[i][j][0], inv, b0), fmaf(acc[i][j][1], inv, b0) };
            *(float2*)&out[((size_t)b*CC + c)*NPIX + m] = v0;
            float2 v1 = { fmaf(acc[i][j][2], inv, b8), fmaf(acc[i][j][3], inv, b8) };
            *(float2*)&out[((size_t)b*CC + c + 8)*NPIX + m] = v1;
        }
    }
}

// ================= launch =================
extern "C" void kernel_launch(void* const* d_in, const int* in_sizes, int n_in,
                              void* d_out, int out_size) {
    const float* x  = (const float*)d_in[0];
    const float* qw = (const float*)d_in[1];
    const float* qb = (const float*)d_in[2];
    const float* kw = (const float*)d_in[3];
    const float* kb = (const float*)d_in[4];
    const float* vw = (const float*)d_in[5];
    const float* vb = (const float*)d_in[6];
    const float* gw = (const float*)d_in[7];
    const float* gb = (const float*)d_in[8];
    float* out = (float*)d_out;

    static bool attr_set = false;
    if (!attr_set) {
        cudaFuncSetAttribute(attn_mma, cudaFuncAttributeMaxDynamicSharedMemorySize, SMEM_BYTES);
        attr_set = true;
    }

    build_weights<<<ROWS_ALL, 256>>>(qw, qb, kw, kb, vw, vb, gw);
    proj_kernel<<<dim3(64, 6, BB), 256>>>(x);
    attn_mma<<<dim3(64, BB), 256, SMEM_BYTES>>>(out, gb);
}

// round 7
// speedup vs baseline: 3.9182x; 1.0112x over previous
#include <cuda_runtime.h>
#include <cuda_bf16.h>
#include <cstdint>

#define NPIX 4096
#define CC   256
#define CQ   64
#define BB   8
#define ROWS_ALL 384
#define LD   72   // smem row stride in halves

// ================= scratch (device globals) =================
__device__ __nv_bfloat16 g_Qh[(size_t)BB*NPIX*CQ];   // [b][n][cq]
__device__ __nv_bfloat16 g_Ql[(size_t)BB*NPIX*CQ];
__device__ __nv_bfloat16 g_Kh[(size_t)BB*NPIX*CQ];   // [b][m][cq]
__device__ __nv_bfloat16 g_Kl[(size_t)BB*NPIX*CQ];
__device__ __nv_bfloat16 g_VGh[(size_t)BB*CC*NPIX];  // [b][c][n]
__device__ __nv_bfloat16 g_VGl[(size_t)BB*CC*NPIX];
__device__ float g_Wall[ROWS_ALL*CC];
__device__ float g_ball[ROWS_ALL];

// ================= PTX helpers =================
__device__ __forceinline__ uint32_t smem_u32(const void* p) {
    uint32_t a;
    asm("{ .reg .u64 t; cvta.to.shared.u64 t, %1; cvt.u32.u64 %0, t; }" : "=r"(a) : "l"(p));
    return a;
}
__device__ __forceinline__ void cpa16(uint32_t dst, const void* src) {
    asm volatile("cp.async.cg.shared.global [%0], [%1], 16;" :: "r"(dst), "l"(src));
}
#define CP_COMMIT() asm volatile("cp.async.commit_group;" ::: "memory")
#define CP_WAIT0()  asm volatile("cp.async.wait_group 0;" ::: "memory")

__device__ __forceinline__ void ldsm4(uint32_t r[4], uint32_t addr) {
    asm volatile("ldmatrix.sync.aligned.m8n8.x4.shared.b16 {%0,%1,%2,%3}, [%4];"
        : "=r"(r[0]), "=r"(r[1]), "=r"(r[2]), "=r"(r[3]) : "r"(addr));
}
__device__ __forceinline__ void mmab(float c[4], const uint32_t a[4],
                                     uint32_t b0, uint32_t b1) {
    asm volatile(
        "mma.sync.aligned.m16n8k16.row.col.f32.bf16.bf16.f32 "
        "{%0,%1,%2,%3}, {%4,%5,%6,%7}, {%8,%9}, {%0,%1,%2,%3};"
        : "+f"(c[0]), "+f"(c[1]), "+f"(c[2]), "+f"(c[3])
        : "r"(a[0]), "r"(a[1]), "r"(a[2]), "r"(a[3]), "r"(b0), "r"(b1));
}
__device__ __forceinline__ uint32_t packbf(float e0, float e1) {
    uint32_t r; asm("cvt.rn.bf16x2.f32 %0, %1, %2;" : "=r"(r) : "f"(e1), "f"(e0)); return r;
}
// elu without /N (deferred), exp via FFMA polynomial
__device__ __forceinline__ float elu_raw(float v) {
    float kf = rintf(v * 1.44269504f);
    float r  = fmaf(kf, -0.693145752f, v);
    r        = fmaf(kf, -1.42860677e-6f, r);
    float p  = 1.38888894e-3f;
    p = fmaf(p, r, 8.33333377e-3f);
    p = fmaf(p, r, 4.16666679e-2f);
    p = fmaf(p, r, 0.166666672f);
    p = fmaf(p, r, 0.5f);
    p = fmaf(p, r, 1.0f);
    p = fmaf(p, r, 1.0f);
    float sc = __uint_as_float((uint32_t)((127 + (int)kf) << 23));
    float e  = fmaf(p, sc, -1.0f);
    return v > 0.f ? v : e;
}

// ================= Kernel 0: weights (gamma folded into V) =================
__global__ void build_weights(const float* __restrict__ qw, const float* __restrict__ qb,
                              const float* __restrict__ kw, const float* __restrict__ kb,
                              const float* __restrict__ vw, const float* __restrict__ vb,
                              const float* __restrict__ gw) {
    int r = blockIdx.x, d = threadIdx.x;
    if (r < CQ) {
        g_Wall[r*CC + d] = qw[r*CC + d];
        if (d == 0) g_ball[r] = qb[r];
    } else if (r < 2*CQ) {
        g_Wall[r*CC + d] = kw[(r-CQ)*CC + d];
        if (d == 0) g_ball[r] = kb[r-CQ];
    } else {
        int c = r - 2*CQ;
        float acc = 0.f;
        for (int cp = 0; cp < CC; ++cp) acc = fmaf(gw[c*CC + cp], vw[cp*CC + d], acc);
        g_Wall[r*CC + d] = acc;
        if (d == 0) {
            float bacc = 0.f;
            for (int cp = 0; cp < CC; ++cp) bacc = fmaf(gw[c*CC + cp], vb[cp], bacc);
            g_ball[r] = bacc;
        }
    }
}

// ================= Kernel 1: projection (fp32), writes split bf16 ==========
__global__ void __launch_bounds__(256) proj_kernel(const float* __restrict__ x) {
    __shared__ float Ws[16][64];
    __shared__ float Xs[16][64];
    int b = blockIdx.z, co0 = blockIdx.y * 64, n0 = blockIdx.x * 64;
    int t = threadIdx.x, tn = t % 16, tco = t / 16;
    const float* xb = x + (size_t)b * CC * NPIX;

    float acc[4][4];
    #pragma unroll
    for (int i = 0; i < 4; i++)
        #pragma unroll
        for (int j = 0; j < 4; j++) acc[i][j] = 0.f;

    for (int k0 = 0; k0 < CC; k0 += 16) {
        {
            int k = t % 16, co = t / 16;
            #pragma unroll
            for (int i = 0; i < 4; i++)
                Ws[k][co + 16*i] = g_Wall[(co0 + co + 16*i)*CC + k0 + k];
        }
        {
            int idx = t * 4, k = idx / 64, n = idx % 64;
            *(float4*)&Xs[k][n] = *(const float4*)&xb[(size_t)(k0 + k)*NPIX + n0 + n];
        }
        __syncthreads();
        #pragma unroll
        for (int k = 0; k < 16; k++) {
            float a[4], bx[4];
            #pragma unroll
            for (int i = 0; i < 4; i++) a[i] = Ws[k][tco + 16*i];
            #pragma unroll
            for (int j = 0; j < 4; j++) bx[j] = Xs[k][tn + 16*j];
            #pragma unroll
            for (int i = 0; i < 4; i++)
                #pragma unroll
                for (int j = 0; j < 4; j++) acc[i][j] = fmaf(a[i], bx[j], acc[i][j]);
        }
        __syncthreads();
    }

    #pragma unroll
    for (int i = 0; i < 4; i++) {
        int co = co0 + tco + 16*i;
        float bias = g_ball[co];
        #pragma unroll
        for (int j = 0; j < 4; j++) {
            int n = n0 + tn + 16*j;
            float s = acc[i][j] + bias;
            __nv_bfloat16 h = __float2bfloat16(s);
            __nv_bfloat16 l = __float2bfloat16(s - __bfloat162float(h));
            if (co < CQ) {
                size_t o = ((size_t)b*NPIX + n)*CQ + co;
                g_Qh[o] = h; g_Ql[o] = l;
            } else if (co < 2*CQ) {
                size_t o = ((size_t)b*NPIX + n)*CQ + (co - CQ);
                g_Kh[o] = h; g_Kl[o] = l;
            } else {
                size_t o = ((size_t)b*CC + (co - 2*CQ))*NPIX + n;
                g_VGh[o] = h; g_VGl[o] = l;
            }
        }
    }
}

// ================= Kernel 2: fused attention, cp.async + ldmatrix ==========
// smem (halves): K(h,l) | S(h,l) | Q(h,l) x2 stages | VG(h,l) x2 stages
#define SM_KH 0
#define SM_KL (64*LD)
#define SM_SH (2*64*LD)
#define SM_SL (3*64*LD)
#define Q_OFF (4*64*LD)          // +s*(128*LD): QH, then QL at +64*LD
#define V_OFF (8*64*LD)          // +s*(512*LD): VH, then VL at +256*LD
#define SMEM_HALVES (8*64*LD + 2*512*LD)
#define SMEM_BYTES  (SMEM_HALVES*2)

__global__ void __launch_bounds__(256) attn_mma(float* __restrict__ out,
                                                const float* __restrict__ gbias) {
    extern __shared__ __nv_bfloat16 sm[];
    const uint32_t sb = smem_u32(sm);
    const int tid = threadIdx.x, wid = tid >> 5, lane = tid & 31;
    const int g = lane >> 2, t4 = lane & 3;
    const int b = blockIdx.y, m0 = blockIdx.x * 64;
    const int lrow = lane & 15, lcol = (lane >> 4) * 8;

    const int w1m = (wid & 1) * 32, w1n = (wid >> 1) * 16;   // GEMM1 [32m x 16n]
    const int w2c = (wid >> 1) * 64, w2m = (wid & 1) * 32;   // GEMM2 [64c x 32m]

    #define SMB(idx) (sb + (uint32_t)(idx) * 2u)

    auto issue_stage = [&](int s, int n0) {
        const uint32_t qh_off = Q_OFF + s*(128*LD), ql_off = qh_off + 64*LD;
        const uint32_t vh_off = V_OFF + s*(512*LD), vl_off = vh_off + 256*LD;
        const __nv_bfloat16* qh = g_Qh + ((size_t)b*NPIX + n0)*CQ;
        const __nv_bfloat16* ql = g_Ql + ((size_t)b*NPIX + n0)*CQ;
        #pragma unroll
        for (int r = 0; r < 2; r++) {
            int id = tid + 256*r, row = id >> 3, ch = (id & 7) * 8;
            cpa16(SMB(qh_off + row*LD + ch), qh + (size_t)row*CQ + ch);
            cpa16(SMB(ql_off + row*LD + ch), ql + (size_t)row*CQ + ch);
        }
        const __nv_bfloat16* vh = g_VGh + (size_t)b*CC*NPIX + n0;
        const __nv_bfloat16* vl = g_VGl + (size_t)b*CC*NPIX + n0;
        #pragma unroll
        for (int r = 0; r < 8; r++) {
            int id = tid + 256*r, c = id >> 3, ch = (id & 7) * 8;
            cpa16(SMB(vh_off + c*LD + ch), vh + (size_t)c*NPIX + ch);
            cpa16(SMB(vl_off + c*LD + ch), vl + (size_t)c*NPIX + ch);
        }
    };

    {   // K tiles via cp.async (part of group 0)
        const __nv_bfloat16* kh = g_Kh + ((size_t)b*NPIX + m0)*CQ;
        const __nv_bfloat16* kl = g_Kl + ((size_t)b*NPIX + m0)*CQ;
        #pragma unroll
        for (int r = 0; r < 2; r++) {
            int id = tid + 256*r, row = id >> 3, ch = (id & 7) * 8;
            cpa16(SMB(SM_KH + row*LD + ch), kh + (size_t)row*CQ + ch);
            cpa16(SMB(SM_KL + row*LD + ch), kl + (size_t)row*CQ + ch);
        }
    }
    issue_stage(0, 0);
    CP_COMMIT();

    float acc[4][4][4];
    #pragma unroll
    for (int i = 0; i < 4; i++)
        #pragma unroll
        for (int j = 0; j < 4; j++)
            #pragma unroll
            for (int q = 0; q < 4; q++) acc[i][j][q] = 0.f;

    for (int it = 0; it < 64; ++it) {
        const int buf = it & 1;
        CP_WAIT0();
        __syncthreads();
        if (it < 63) { issue_stage(buf ^ 1, (it + 1) * 64); CP_COMMIT(); }

        const uint32_t QH = Q_OFF + buf*(128*LD), QL = QH + 64*LD;
        const uint32_t VH = V_OFF + buf*(512*LD), VL = VH + 256*LD;

        // ---- GEMM1: D1[m][n] = K·Q, 3-product split ----
        float sacc[2][2][4];
        #pragma unroll
        for (int i = 0; i < 2; i++)
            #pragma unroll
            for (int j = 0; j < 2; j++)
                #pragma unroll
                for (int q = 0; q < 4; q++) sacc[i][j][q] = 0.f;

        #pragma unroll
        for (int kk = 0; kk < 4; kk++) {
            const int C = kk * 16 + lcol;
            uint32_t kh0[4], kh1[4], kl0[4], kl1[4], qh[4], ql[4];
            ldsm4(kh0, SMB(SM_KH + (w1m      + lrow)*LD + C));
            ldsm4(kh1, SMB(SM_KH + (w1m + 16 + lrow)*LD + C));
            ldsm4(kl0, SMB(SM_KL + (w1m      + lrow)*LD + C));
            ldsm4(kl1, SMB(SM_KL + (w1m + 16 + lrow)*LD + C));
            ldsm4(qh,  SMB(QH    + (w1n      + lrow)*LD + C));
            ldsm4(ql,  SMB(QL    + (w1n      + lrow)*LD + C));
            // n-tile0 b = {q[0],q[2]}, n-tile1 b = {q[1],q[3]}
            mmab(sacc[0][0], kh0, qh[0], qh[2]);
            mmab(sacc[0][1], kh0, qh[1], qh[3]);
            mmab(sacc[1][0], kh1, qh[0], qh[2]);
            mmab(sacc[1][1], kh1, qh[1], qh[3]);
            mmab(sacc[0][0], kl0, qh[0], qh[2]);
            mmab(sacc[0][1], kl0, qh[1], qh[3]);
            mmab(sacc[1][0], kl1, qh[0], qh[2]);
            mmab(sacc[1][1], kl1, qh[1], qh[3]);
            mmab(sacc[0][0], kh0, ql[0], ql[2]);
            mmab(sacc[0][1], kh0, ql[1], ql[3]);
            mmab(sacc[1][0], kh1, ql[0], ql[2]);
            mmab(sacc[1][1], kh1, ql[1], ql[3]);
        }

        // ---- elu + split + store S (hi/lo), layout [m][n] ----
        #pragma unroll
        for (int i = 0; i < 2; i++)
            #pragma unroll
            for (int j = 0; j < 2; j++) {
                int row = w1m + 16*i + g;
                int col = w1n + 8*j + t4*2;
                {
                    float e0 = elu_raw(sacc[i][j][0]);
                    float e1 = elu_raw(sacc[i][j][1]);
                    uint32_t ph = packbf(e0, e1);
                    float l0 = e0 - __uint_as_float(ph << 16);
                    float l1 = e1 - __uint_as_float(ph & 0xFFFF0000u);
                    *(uint32_t*)&sm[SM_SH + row*LD + col] = ph;
                    *(uint32_t*)&sm[SM_SL + row*LD + col] = packbf(l0, l1);
                }
                {
                    float e0 = elu_raw(sacc[i][j][2]);
                    float e1 = elu_raw(sacc[i][j][3]);
                    uint32_t ph = packbf(e0, e1);
                    float l0 = e0 - __uint_as_float(ph << 16);
                    float l1 = e1 - __uint_as_float(ph & 0xFFFF0000u);
                    *(uint32_t*)&sm[SM_SH + (row+8)*LD + col] = ph;
                    *(uint32_t*)&sm[SM_SL + (row+8)*LD + col] = packbf(l0, l1);
                }
            }
        __syncthreads();

        // ---- GEMM2: O[c][m] += VG·S ----
        #pragma unroll
        for (int kk = 0; kk < 4; kk++) {
            const int C = kk * 16 + lcol;
            uint32_t vh[4][4], vl[4][4], sh0[4], sh1[4], sl0[4], sl1[4];
            #pragma unroll
            for (int i = 0; i < 4; i++) {
                ldsm4(vh[i], SMB(VH + (w2c + 16*i + lrow)*LD + C));
                ldsm4(vl[i], SMB(VL + (w2c + 16*i + lrow)*LD + C));
            }
            ldsm4(sh0, SMB(SM_SH + (w2m      + lrow)*LD + C));
            ldsm4(sh1, SMB(SM_SH + (w2m + 16 + lrow)*LD + C));
            ldsm4(sl0, SMB(SM_SL + (w2m      + lrow)*LD + C));
            ldsm4(sl1, SMB(SM_SL + (w2m + 16 + lrow)*LD + C));
            #pragma unroll
            for (int i = 0; i < 4; i++) {
                mmab(acc[i][0], vh[i], sh0[0], sh0[2]);
                mmab(acc[i][1], vh[i], sh0[1], sh0[3]);
                mmab(acc[i][2], vh[i], sh1[0], sh1[2]);
                mmab(acc[i][3], vh[i], sh1[1], sh1[3]);
                mmab(acc[i][0], vl[i], sh0[0], sh0[2]);
                mmab(acc[i][1], vl[i], sh0[1], sh0[3]);
                mmab(acc[i][2], vl[i], sh1[0], sh1[2]);
                mmab(acc[i][3], vl[i], sh1[1], sh1[3]);
                mmab(acc[i][0], vh[i], sl0[0], sl0[2]);
                mmab(acc[i][1], vh[i], sl0[1], sl0[3]);
                mmab(acc[i][2], vh[i], sl1[0], sl1[2]);
                mmab(acc[i][3], vh[i], sl1[1], sl1[3]);
            }
        }
    }

    // ---- epilogue: out = acc/4096 + gbias[c] ----
    const float inv = 1.0f / 4096.0f;
    #pragma unroll
    for (int i = 0; i < 4; i++) {
        int c  = w2c + 16*i + g;
        float b0 = gbias[c], b8 = gbias[c + 8];
        #pragma unroll
        for (int j = 0; j < 4; j++) {
            int m = m0 + w2m + 8*j + t4*2;
            float2 v0 = { fmaf(acc[i][j][0], inv, b0), fmaf(acc[i][j][1], inv, b0) };
            *(float2*)&out[((size_t)b*CC + c)*NPIX + m] = v0;
            float2 v1 = { fmaf(acc[i][j][2], inv, b8), fmaf(acc[i][j][3], inv, b8) };
            *(float2*)&out[((size_t)b*CC + c + 8)*NPIX + m] = v1;
        }
    }
}

// ================= launch =================
extern "C" void kernel_launch(void* const* d_in, const int* in_sizes, int n_in,
                              void* d_out, int out_size) {
    const float* x  = (const float*)d_in[0];
    const float* qw = (const float*)d_in[1];
    const float* qb = (const float*)d_in[2];
    const float* kw = (const float*)d_in[3];
    const float* kb = (const float*)d_in[4];
    const float* vw = (const float*)d_in[5];
    const float* vb = (const float*)d_in[6];
    const float* gw = (const float*)d_in[7];
    const float* gb = (const float*)d_in[8];
    float* out = (float*)d_out;

    cudaFuncSetAttribute(attn_mma, cudaFuncAttributeMaxDynamicSharedMemorySize, SMEM_BYTES);

    build_weights<<<ROWS_ALL, 256>>>(qw, qb, kw, kb, vw, vb, gw);
    proj_kernel<<<dim3(64, 6, BB), 256>>>(x);
    attn_mma<<<dim3(64, BB), 256, SMEM_BYTES>>>(out, gb);
}